// round 8
// baseline (speedup 1.0000x reference)
#include <cuda_runtime.h>
#include <math.h>
#include <stdint.h>

// Problem constants
#define BATCH 2
#define SEQ   2048
#define DMODEL 1024
#define NHEAD 16
#define HDIM  64
#define MTOT  (BATCH*SEQ)            // 4096
#define QKV_N (3*DMODEL)             // 3072
#define GK    1024

// Scratch (allocation-free: __device__ globals)
__device__ float g_qkv[3u * 4194304u];   // [3][B][H][S][hd]
__device__ float g_attn[4194304u];       // [B][S][H*hd] == [4096][1024]

__device__ __forceinline__ float f32_to_tf32f(float x) {
    uint32_t r;
    asm("cvt.rna.tf32.f32 %0, %1;" : "=r"(r) : "f"(x));
    return __uint_as_float(r);
}

__device__ __forceinline__ float ex2f(float x) {
    float r;
    asm("ex2.approx.ftz.f32 %0, %1;" : "=f"(r) : "f"(x));
    return r;
}

__device__ __forceinline__ void mma_tf32_16x8x8(float* c,
                                                float a0, float a1, float a2, float a3,
                                                float b0, float b1) {
    asm volatile(
        "mma.sync.aligned.m16n8k8.row.col.f32.tf32.tf32.f32 "
        "{%0,%1,%2,%3}, {%4,%5,%6,%7}, {%8,%9}, {%0,%1,%2,%3};"
        : "+f"(c[0]), "+f"(c[1]), "+f"(c[2]), "+f"(c[3])
        : "r"(__float_as_uint(a0)), "r"(__float_as_uint(a1)),
          "r"(__float_as_uint(a2)), "r"(__float_as_uint(a3)),
          "r"(__float_as_uint(b0)), "r"(__float_as_uint(b1)));
}

// ---------------------------------------------------------------------------
// tf32 mma.sync GEMM — R7 version with ONE __syncthreads per k-tile
// (compute reads buf cur, stores write buf cur^1: disjoint, no sync needed
// between them; only store -> next-iteration-compute needs the barrier).
// ---------------------------------------------------------------------------
#define LDS_STRIDE 20

__global__ __launch_bounds__(256, 2) void gemm_tc_kernel(
    const float* __restrict__ A_arg,
    const float* __restrict__ W,
    const float* __restrict__ bias,
    float* __restrict__ out,
    int mode)
{
    __shared__ float As[2][128 * LDS_STRIDE];
    __shared__ float Bs[2][128 * LDS_STRIDE];

    const float* A = (A_arg != nullptr) ? A_arg : (const float*)g_attn;

    int tid  = threadIdx.x;
    int wid  = tid >> 5;
    int lane = tid & 31;
    int wm   = wid >> 2;
    int wn   = wid & 3;
    int g    = lane >> 2;
    int tig  = lane & 3;

    int m0 = blockIdx.y * 128;
    int n0 = blockIdx.x * 128;

    int ar0 = tid >> 2;
    int ar1 = ar0 + 64;
    int ac  = (tid & 3) * 4;

    const float* Ab = A + (size_t)m0 * GK + ac;
    const float* Wb = W + (size_t)n0 * GK + ac;

    float c[4][4][4];
#pragma unroll
    for (int i = 0; i < 4; i++)
#pragma unroll
        for (int j = 0; j < 4; j++)
#pragma unroll
            for (int q = 0; q < 4; q++) c[i][j][q] = 0.f;

    // prologue: tile 0 -> buffer 0
    {
        float4 a0 = *(const float4*)(Ab + (size_t)ar0 * GK);
        float4 a1 = *(const float4*)(Ab + (size_t)ar1 * GK);
        float4 b0 = *(const float4*)(Wb + (size_t)ar0 * GK);
        float4 b1 = *(const float4*)(Wb + (size_t)ar1 * GK);
        float* as = As[0]; float* bs = Bs[0];
        float4 t;
        t.x = f32_to_tf32f(a0.x); t.y = f32_to_tf32f(a0.y);
        t.z = f32_to_tf32f(a0.z); t.w = f32_to_tf32f(a0.w);
        *(float4*)&as[ar0 * LDS_STRIDE + ac] = t;
        t.x = f32_to_tf32f(a1.x); t.y = f32_to_tf32f(a1.y);
        t.z = f32_to_tf32f(a1.z); t.w = f32_to_tf32f(a1.w);
        *(float4*)&as[ar1 * LDS_STRIDE + ac] = t;
        t.x = f32_to_tf32f(b0.x); t.y = f32_to_tf32f(b0.y);
        t.z = f32_to_tf32f(b0.z); t.w = f32_to_tf32f(b0.w);
        *(float4*)&bs[ar0 * LDS_STRIDE + ac] = t;
        t.x = f32_to_tf32f(b1.x); t.y = f32_to_tf32f(b1.y);
        t.z = f32_to_tf32f(b1.z); t.w = f32_to_tf32f(b1.w);
        *(float4*)&bs[ar1 * LDS_STRIDE + ac] = t;
    }
    __syncthreads();

    const int NT = GK / 16;
    for (int kt = 0; kt < NT; kt++) {
        int cur = kt & 1;
        float4 na0, na1, nb0, nb1;
        if (kt < NT - 1) {
            int ko = (kt + 1) * 16;
            na0 = *(const float4*)(Ab + (size_t)ar0 * GK + ko);
            na1 = *(const float4*)(Ab + (size_t)ar1 * GK + ko);
            nb0 = *(const float4*)(Wb + (size_t)ar0 * GK + ko);
            nb1 = *(const float4*)(Wb + (size_t)ar1 * GK + ko);
        }

        const float* as = As[cur];
        const float* bs = Bs[cur];
#pragma unroll
        for (int k8 = 0; k8 < 2; k8++) {
            int kc = k8 * 8 + tig;
            float af[4][4], bf[4][2];
#pragma unroll
            for (int mt = 0; mt < 4; mt++) {
                int r = wm * 64 + mt * 16 + g;
                af[mt][0] = as[(r + 0) * LDS_STRIDE + kc];
                af[mt][1] = as[(r + 8) * LDS_STRIDE + kc];
                af[mt][2] = as[(r + 0) * LDS_STRIDE + kc + 4];
                af[mt][3] = as[(r + 8) * LDS_STRIDE + kc + 4];
            }
#pragma unroll
            for (int nt = 0; nt < 4; nt++) {
                int r = wn * 32 + nt * 8 + g;
                bf[nt][0] = bs[r * LDS_STRIDE + kc];
                bf[nt][1] = bs[r * LDS_STRIDE + kc + 4];
            }
#pragma unroll
            for (int mt = 0; mt < 4; mt++)
#pragma unroll
                for (int nt = 0; nt < 4; nt++)
                    mma_tf32_16x8x8(c[mt][nt],
                                    af[mt][0], af[mt][1], af[mt][2], af[mt][3],
                                    bf[nt][0], bf[nt][1]);
        }

        if (kt < NT - 1) {
            float* asn = As[cur ^ 1]; float* bsn = Bs[cur ^ 1];
            float4 t;
            t.x = f32_to_tf32f(na0.x); t.y = f32_to_tf32f(na0.y);
            t.z = f32_to_tf32f(na0.z); t.w = f32_to_tf32f(na0.w);
            *(float4*)&asn[ar0 * LDS_STRIDE + ac] = t;
            t.x = f32_to_tf32f(na1.x); t.y = f32_to_tf32f(na1.y);
            t.z = f32_to_tf32f(na1.z); t.w = f32_to_tf32f(na1.w);
            *(float4*)&asn[ar1 * LDS_STRIDE + ac] = t;
            t.x = f32_to_tf32f(nb0.x); t.y = f32_to_tf32f(nb0.y);
            t.z = f32_to_tf32f(nb0.z); t.w = f32_to_tf32f(nb0.w);
            *(float4*)&bsn[ar0 * LDS_STRIDE + ac] = t;
            t.x = f32_to_tf32f(nb1.x); t.y = f32_to_tf32f(nb1.y);
            t.z = f32_to_tf32f(nb1.z); t.w = f32_to_tf32f(nb1.w);
            *(float4*)&bsn[ar1 * LDS_STRIDE + ac] = t;
        }
        __syncthreads();
    }

#pragma unroll
    for (int mt = 0; mt < 4; mt++) {
#pragma unroll
        for (int half = 0; half < 2; half++) {
            int m = m0 + wm * 64 + mt * 16 + g + half * 8;
            int b = m >> 11;
            int s = m & 2047;
#pragma unroll
            for (int nt = 0; nt < 4; nt++) {
                int n = n0 + wn * 32 + nt * 8 + 2 * tig;
                float2 v;
                v.x = c[mt][nt][half * 2 + 0] + bias[n + 0];
                v.y = c[mt][nt][half * 2 + 1] + bias[n + 1];
                if (mode == 0) {
                    int which = n >> 10;
                    int rr = n & 1023;
                    int h = rr >> 6;
                    int d = rr & 63;
                    *(float2*)&g_qkv[(size_t)which * 4194304u +
                                     ((size_t)((b << 4) + h) * SEQ + s) * HDIM + d] = v;
                } else {
                    *(float2*)&out[(size_t)m * DMODEL + n] = v;
                }
            }
        }
    }
}

// ---------------------------------------------------------------------------
// Flash attention with tf32 mma.sync.
// R8: double-buffered Ks/Vs, register prefetch (K during S-phase, V during
// PV-phase), ONE __syncthreads per key tile, exp2 softmax (log2e folded
// into the Q scale).
// Smem: Ks[2][64][68] | Vs[2][64][72] | Ps[128][68] = 106496 bytes.
// ---------------------------------------------------------------------------
#define KS_STRIDE 68
#define VS_STRIDE 72
#define PS_STRIDE 68
#define FLASH_SMEM ((2*64*KS_STRIDE + 2*64*VS_STRIDE + 128*PS_STRIDE) * 4)

__global__ __launch_bounds__(256, 2) void flash_tc_kernel()
{
    extern __shared__ float smf[];
    float* KsB[2]; float* VsB[2];
    KsB[0] = smf;
    KsB[1] = smf + 64 * KS_STRIDE;
    VsB[0] = smf + 2 * 64 * KS_STRIDE;
    VsB[1] = smf + 2 * 64 * KS_STRIDE + 64 * VS_STRIDE;
    float* Ps = smf + 2 * 64 * KS_STRIDE + 2 * 64 * VS_STRIDE;  // [128][PS_STRIDE]

    int tid  = threadIdx.x;
    int w    = tid >> 5;
    int lane = tid & 31;
    int g    = lane >> 2;          // 0..7
    int tig  = lane & 3;           // 0..3

    int q0 = blockIdx.x * 128;
    int h  = blockIdx.y;
    int b  = blockIdx.z;

    // 1/sqrt(64) * log2(e): softmax computed in base-2 domain.
    const float scale = 0.125f * 1.4426950408889634f;

    const float* Qg = g_qkv + 0u * 4194304u + (size_t)((b << 4) + h) * SEQ * HDIM;
    const float* Kg = g_qkv + 1u * 4194304u + (size_t)((b << 4) + h) * SEQ * HDIM;
    const float* Vg = g_qkv + 2u * 4194304u + (size_t)((b << 4) + h) * SEQ * HDIM;

    // per-thread load coords for K/V tiles: 4 float4 each
    int lrow = tid >> 4;           // 0..15 (row block of 4 rows per it? no: see below)
    // j = tid + it*256 -> row = j>>4 (0..63), c4 = (j&15)*4
    int lc4  = (tid & 15) << 2;

    // Q fragments, register-resident (scale + tf32 folded)
    int qrow = q0 + w * 16;
    float qf[8][4];
#pragma unroll
    for (int kc = 0; kc < 8; kc++) {
        int d0 = kc * 8 + tig;
        qf[kc][0] = f32_to_tf32f(Qg[(size_t)(qrow + g)     * HDIM + d0]     * scale);
        qf[kc][1] = f32_to_tf32f(Qg[(size_t)(qrow + g + 8) * HDIM + d0]     * scale);
        qf[kc][2] = f32_to_tf32f(Qg[(size_t)(qrow + g)     * HDIM + d0 + 4] * scale);
        qf[kc][3] = f32_to_tf32f(Qg[(size_t)(qrow + g + 8) * HDIM + d0 + 4] * scale);
    }

    float m0r = -1e30f, m1r = -1e30f, l0r = 0.f, l1r = 0.f;
    float ov[8][4];
#pragma unroll
    for (int nt = 0; nt < 8; nt++)
#pragma unroll
        for (int q = 0; q < 4; q++) ov[nt][q] = 0.f;

    float* Psw = Ps + w * 16 * PS_STRIDE;   // per-warp private slab

    // Prologue: tile 0 into buffer 0
    {
        const float* Kt = Kg;
        const float* Vt = Vg;
#pragma unroll
        for (int it = 0; it < 4; it++) {
            int row = lrow + it * 16;
            float4 kv = *(const float4*)(Kt + row * HDIM + lc4);
            float4 vv = *(const float4*)(Vt + row * HDIM + lc4);
            float4 t;
            t.x = f32_to_tf32f(kv.x); t.y = f32_to_tf32f(kv.y);
            t.z = f32_to_tf32f(kv.z); t.w = f32_to_tf32f(kv.w);
            *(float4*)&KsB[0][row * KS_STRIDE + lc4] = t;
            t.x = f32_to_tf32f(vv.x); t.y = f32_to_tf32f(vv.y);
            t.z = f32_to_tf32f(vv.z); t.w = f32_to_tf32f(vv.w);
            *(float4*)&VsB[0][row * VS_STRIDE + lc4] = t;
        }
    }
    __syncthreads();

    const int NT = SEQ / 64;   // 32
    for (int kt = 0; kt < NT; kt++) {
        int cur = kt & 1;
        const float* Ks = KsB[cur];
        const float* Vs = VsB[cur];

        // Prefetch K(kt+1) into registers (latency hidden by S + softmax)
        float4 kreg[4];
        if (kt < NT - 1) {
            const float* Kn = Kg + (size_t)(kt + 1) * 64 * HDIM;
#pragma unroll
            for (int it = 0; it < 4; it++)
                kreg[it] = *(const float4*)(Kn + (lrow + it * 16) * HDIM + lc4);
        }

        // S = Q K^T
        float sc[8][4];
#pragma unroll
        for (int nt = 0; nt < 8; nt++)
#pragma unroll
            for (int q = 0; q < 4; q++) sc[nt][q] = 0.f;
#pragma unroll
        for (int kc = 0; kc < 8; kc++) {
            int d0 = kc * 8 + tig;
#pragma unroll
            for (int nt = 0; nt < 8; nt++) {
                int key = nt * 8 + g;
                float b0 = Ks[key * KS_STRIDE + d0];
                float b1 = Ks[key * KS_STRIDE + d0 + 4];
                mma_tf32_16x8x8(sc[nt], qf[kc][0], qf[kc][1], qf[kc][2], qf[kc][3], b0, b1);
            }
        }

        // Online softmax (base-2). Rows qrow+g (frag 0,1), qrow+g+8 (frag 2,3).
        float rm0 = -1e30f, rm1 = -1e30f;
#pragma unroll
        for (int nt = 0; nt < 8; nt++) {
            rm0 = fmaxf(rm0, fmaxf(sc[nt][0], sc[nt][1]));
            rm1 = fmaxf(rm1, fmaxf(sc[nt][2], sc[nt][3]));
        }
        rm0 = fmaxf(rm0, __shfl_xor_sync(0xffffffffu, rm0, 1));
        rm0 = fmaxf(rm0, __shfl_xor_sync(0xffffffffu, rm0, 2));
        rm1 = fmaxf(rm1, __shfl_xor_sync(0xffffffffu, rm1, 1));
        rm1 = fmaxf(rm1, __shfl_xor_sync(0xffffffffu, rm1, 2));

        float nm0 = fmaxf(m0r, rm0);
        float nm1 = fmaxf(m1r, rm1);
        float alpha0 = ex2f(m0r - nm0);
        float alpha1 = ex2f(m1r - nm1);
        m0r = nm0; m1r = nm1;

        float rs0 = 0.f, rs1 = 0.f;
#pragma unroll
        for (int nt = 0; nt < 8; nt++) {
            sc[nt][0] = ex2f(sc[nt][0] - nm0);
            sc[nt][1] = ex2f(sc[nt][1] - nm0);
            sc[nt][2] = ex2f(sc[nt][2] - nm1);
            sc[nt][3] = ex2f(sc[nt][3] - nm1);
            rs0 += sc[nt][0] + sc[nt][1];
            rs1 += sc[nt][2] + sc[nt][3];
        }
        rs0 += __shfl_xor_sync(0xffffffffu, rs0, 1);
        rs0 += __shfl_xor_sync(0xffffffffu, rs0, 2);
        rs1 += __shfl_xor_sync(0xffffffffu, rs1, 1);
        rs1 += __shfl_xor_sync(0xffffffffu, rs1, 2);
        l0r = l0r * alpha0 + rs0;
        l1r = l1r * alpha1 + rs1;

#pragma unroll
        for (int nt = 0; nt < 8; nt++) {
            ov[nt][0] *= alpha0; ov[nt][1] *= alpha0;
            ov[nt][2] *= alpha1; ov[nt][3] *= alpha1;
        }

        // Stage P (tf32) into per-warp slab
#pragma unroll
        for (int nt = 0; nt < 8; nt++) {
            float2 p0, p1;
            p0.x = f32_to_tf32f(sc[nt][0]); p0.y = f32_to_tf32f(sc[nt][1]);
            p1.x = f32_to_tf32f(sc[nt][2]); p1.y = f32_to_tf32f(sc[nt][3]);
            *(float2*)&Psw[g       * PS_STRIDE + nt * 8 + 2 * tig] = p0;
            *(float2*)&Psw[(g + 8) * PS_STRIDE + nt * 8 + 2 * tig] = p1;
        }
        __syncwarp();

        // Prefetch V(kt+1) (latency hidden by PV phase; sc registers now dead)
        float4 vreg[4];
        if (kt < NT - 1) {
            const float* Vn = Vg + (size_t)(kt + 1) * 64 * HDIM;
#pragma unroll
            for (int it = 0; it < 4; it++)
                vreg[it] = *(const float4*)(Vn + (lrow + it * 16) * HDIM + lc4);
        }

        // O += P V
#pragma unroll
        for (int kc = 0; kc < 8; kc++) {
            int k0 = kc * 8 + tig;
            float a0 = Psw[g       * PS_STRIDE + k0];
            float a1 = Psw[(g + 8) * PS_STRIDE + k0];
            float a2 = Psw[g       * PS_STRIDE + k0 + 4];
            float a3 = Psw[(g + 8) * PS_STRIDE + k0 + 4];
#pragma unroll
            for (int nt = 0; nt < 8; nt++) {
                float b0 = Vs[k0       * VS_STRIDE + nt * 8 + g];
                float b1 = Vs[(k0 + 4) * VS_STRIDE + nt * 8 + g];
                mma_tf32_16x8x8(ov[nt], a0, a1, a2, a3, b0, b1);
            }
        }

        // Store prefetched K/V into the other buffer (disjoint from cur)
        if (kt < NT - 1) {
            float* Ksn = KsB[cur ^ 1];
            float* Vsn = VsB[cur ^ 1];
#pragma unroll
            for (int it = 0; it < 4; it++) {
                int row = lrow + it * 16;
                float4 t;
                t.x = f32_to_tf32f(kreg[it].x); t.y = f32_to_tf32f(kreg[it].y);
                t.z = f32_to_tf32f(kreg[it].z); t.w = f32_to_tf32f(kreg[it].w);
                *(float4*)&Ksn[row * KS_STRIDE + lc4] = t;
                t.x = f32_to_tf32f(vreg[it].x); t.y = f32_to_tf32f(vreg[it].y);
                t.z = f32_to_tf32f(vreg[it].z); t.w = f32_to_tf32f(vreg[it].w);
                *(float4*)&Vsn[row * VS_STRIDE + lc4] = t;
            }
        }
        __syncthreads();
    }

    // Epilogue: normalize, write to [B][S][H*hd]
    float inv0 = 1.0f / l0r;
    float inv1 = 1.0f / l1r;
    int s0 = qrow + g;
    int s1 = qrow + g + 8;
#pragma unroll
    for (int nt = 0; nt < 8; nt++) {
        int d = nt * 8 + 2 * tig;
        float2 v0, v1;
        v0.x = ov[nt][0] * inv0; v0.y = ov[nt][1] * inv0;
        v1.x = ov[nt][2] * inv1; v1.y = ov[nt][3] * inv1;
        *(float2*)&g_attn[((size_t)(b * SEQ + s0)) * DMODEL + h * HDIM + d] = v0;
        *(float2*)&g_attn[((size_t)(b * SEQ + s1)) * DMODEL + h * HDIM + d] = v1;
    }
}

// ---------------------------------------------------------------------------
// Launch
// ---------------------------------------------------------------------------
extern "C" void kernel_launch(void* const* d_in, const int* in_sizes, int n_in,
                              void* d_out, int out_size)
{
    const float* x      = (const float*)d_in[0];
    const float* w_qkv  = (const float*)d_in[1];
    const float* b_qkv  = (const float*)d_in[2];
    const float* w_proj = (const float*)d_in[3];
    const float* b_proj = (const float*)d_in[4];
    float* out = (float*)d_out;

    cudaFuncSetAttribute(flash_tc_kernel, cudaFuncAttributeMaxDynamicSharedMemorySize, FLASH_SMEM);

    gemm_tc_kernel<<<dim3(QKV_N / 128, MTOT / 128), 256>>>(x, w_qkv, b_qkv, nullptr, 0);
    flash_tc_kernel<<<dim3(SEQ / 128, NHEAD, BATCH), 256, FLASH_SMEM>>>();
    gemm_tc_kernel<<<dim3(DMODEL / 128, MTOT / 128), 256>>>(nullptr, w_proj, b_proj, out, 1);
}

// round 9
// speedup vs baseline: 1.2435x; 1.2435x over previous
#include <cuda_runtime.h>
#include <math.h>
#include <stdint.h>

// Problem constants
#define BATCH 2
#define SEQ   2048
#define DMODEL 1024
#define NHEAD 16
#define HDIM  64
#define MTOT  (BATCH*SEQ)            // 4096
#define QKV_N (3*DMODEL)             // 3072
#define GK    1024

// Scratch (allocation-free: __device__ globals)
__device__ float g_qkv[3u * 4194304u];   // [3][B][H][S][hd]
__device__ float g_attn[4194304u];       // [B][S][H*hd] == [4096][1024]

__device__ __forceinline__ float f32_to_tf32f(float x) {
    uint32_t r;
    asm("cvt.rna.tf32.f32 %0, %1;" : "=r"(r) : "f"(x));
    return __uint_as_float(r);
}

__device__ __forceinline__ float ex2f(float x) {
    float r;
    asm("ex2.approx.ftz.f32 %0, %1;" : "=f"(r) : "f"(x));
    return r;
}

__device__ __forceinline__ void mma_tf32_16x8x8(float* c,
                                                float a0, float a1, float a2, float a3,
                                                float b0, float b1) {
    asm volatile(
        "mma.sync.aligned.m16n8k8.row.col.f32.tf32.tf32.f32 "
        "{%0,%1,%2,%3}, {%4,%5,%6,%7}, {%8,%9}, {%0,%1,%2,%3};"
        : "+f"(c[0]), "+f"(c[1]), "+f"(c[2]), "+f"(c[3])
        : "r"(__float_as_uint(a0)), "r"(__float_as_uint(a1)),
          "r"(__float_as_uint(a2)), "r"(__float_as_uint(a3)),
          "r"(__float_as_uint(b0)), "r"(__float_as_uint(b1)));
}

// ---------------------------------------------------------------------------
// tf32 mma.sync GEMM — R8 version (one __syncthreads per k-tile), proven win.
// ---------------------------------------------------------------------------
#define LDS_STRIDE 20

__global__ __launch_bounds__(256, 2) void gemm_tc_kernel(
    const float* __restrict__ A_arg,
    const float* __restrict__ W,
    const float* __restrict__ bias,
    float* __restrict__ out,
    int mode)
{
    __shared__ float As[2][128 * LDS_STRIDE];
    __shared__ float Bs[2][128 * LDS_STRIDE];

    const float* A = (A_arg != nullptr) ? A_arg : (const float*)g_attn;

    int tid  = threadIdx.x;
    int wid  = tid >> 5;
    int lane = tid & 31;
    int wm   = wid >> 2;
    int wn   = wid & 3;
    int g    = lane >> 2;
    int tig  = lane & 3;

    int m0 = blockIdx.y * 128;
    int n0 = blockIdx.x * 128;

    int ar0 = tid >> 2;
    int ar1 = ar0 + 64;
    int ac  = (tid & 3) * 4;

    const float* Ab = A + (size_t)m0 * GK + ac;
    const float* Wb = W + (size_t)n0 * GK + ac;

    float c[4][4][4];
#pragma unroll
    for (int i = 0; i < 4; i++)
#pragma unroll
        for (int j = 0; j < 4; j++)
#pragma unroll
            for (int q = 0; q < 4; q++) c[i][j][q] = 0.f;

    // prologue: tile 0 -> buffer 0
    {
        float4 a0 = *(const float4*)(Ab + (size_t)ar0 * GK);
        float4 a1 = *(const float4*)(Ab + (size_t)ar1 * GK);
        float4 b0 = *(const float4*)(Wb + (size_t)ar0 * GK);
        float4 b1 = *(const float4*)(Wb + (size_t)ar1 * GK);
        float* as = As[0]; float* bs = Bs[0];
        float4 t;
        t.x = f32_to_tf32f(a0.x); t.y = f32_to_tf32f(a0.y);
        t.z = f32_to_tf32f(a0.z); t.w = f32_to_tf32f(a0.w);
        *(float4*)&as[ar0 * LDS_STRIDE + ac] = t;
        t.x = f32_to_tf32f(a1.x); t.y = f32_to_tf32f(a1.y);
        t.z = f32_to_tf32f(a1.z); t.w = f32_to_tf32f(a1.w);
        *(float4*)&as[ar1 * LDS_STRIDE + ac] = t;
        t.x = f32_to_tf32f(b0.x); t.y = f32_to_tf32f(b0.y);
        t.z = f32_to_tf32f(b0.z); t.w = f32_to_tf32f(b0.w);
        *(float4*)&bs[ar0 * LDS_STRIDE + ac] = t;
        t.x = f32_to_tf32f(b1.x); t.y = f32_to_tf32f(b1.y);
        t.z = f32_to_tf32f(b1.z); t.w = f32_to_tf32f(b1.w);
        *(float4*)&bs[ar1 * LDS_STRIDE + ac] = t;
    }
    __syncthreads();

    const int NT = GK / 16;
    for (int kt = 0; kt < NT; kt++) {
        int cur = kt & 1;
        float4 na0, na1, nb0, nb1;
        if (kt < NT - 1) {
            int ko = (kt + 1) * 16;
            na0 = *(const float4*)(Ab + (size_t)ar0 * GK + ko);
            na1 = *(const float4*)(Ab + (size_t)ar1 * GK + ko);
            nb0 = *(const float4*)(Wb + (size_t)ar0 * GK + ko);
            nb1 = *(const float4*)(Wb + (size_t)ar1 * GK + ko);
        }

        const float* as = As[cur];
        const float* bs = Bs[cur];
#pragma unroll
        for (int k8 = 0; k8 < 2; k8++) {
            int kc = k8 * 8 + tig;
            float af[4][4], bf[4][2];
#pragma unroll
            for (int mt = 0; mt < 4; mt++) {
                int r = wm * 64 + mt * 16 + g;
                af[mt][0] = as[(r + 0) * LDS_STRIDE + kc];
                af[mt][1] = as[(r + 8) * LDS_STRIDE + kc];
                af[mt][2] = as[(r + 0) * LDS_STRIDE + kc + 4];
                af[mt][3] = as[(r + 8) * LDS_STRIDE + kc + 4];
            }
#pragma unroll
            for (int nt = 0; nt < 4; nt++) {
                int r = wn * 32 + nt * 8 + g;
                bf[nt][0] = bs[r * LDS_STRIDE + kc];
                bf[nt][1] = bs[r * LDS_STRIDE + kc + 4];
            }
#pragma unroll
            for (int mt = 0; mt < 4; mt++)
#pragma unroll
                for (int nt = 0; nt < 4; nt++)
                    mma_tf32_16x8x8(c[mt][nt],
                                    af[mt][0], af[mt][1], af[mt][2], af[mt][3],
                                    bf[nt][0], bf[nt][1]);
        }

        if (kt < NT - 1) {
            float* asn = As[cur ^ 1]; float* bsn = Bs[cur ^ 1];
            float4 t;
            t.x = f32_to_tf32f(na0.x); t.y = f32_to_tf32f(na0.y);
            t.z = f32_to_tf32f(na0.z); t.w = f32_to_tf32f(na0.w);
            *(float4*)&asn[ar0 * LDS_STRIDE + ac] = t;
            t.x = f32_to_tf32f(na1.x); t.y = f32_to_tf32f(na1.y);
            t.z = f32_to_tf32f(na1.z); t.w = f32_to_tf32f(na1.w);
            *(float4*)&asn[ar1 * LDS_STRIDE + ac] = t;
            t.x = f32_to_tf32f(nb0.x); t.y = f32_to_tf32f(nb0.y);
            t.z = f32_to_tf32f(nb0.z); t.w = f32_to_tf32f(nb0.w);
            *(float4*)&bsn[ar0 * LDS_STRIDE + ac] = t;
            t.x = f32_to_tf32f(nb1.x); t.y = f32_to_tf32f(nb1.y);
            t.z = f32_to_tf32f(nb1.z); t.w = f32_to_tf32f(nb1.w);
            *(float4*)&bsn[ar1 * LDS_STRIDE + ac] = t;
        }
        __syncthreads();
    }

#pragma unroll
    for (int mt = 0; mt < 4; mt++) {
#pragma unroll
        for (int half = 0; half < 2; half++) {
            int m = m0 + wm * 64 + mt * 16 + g + half * 8;
            int b = m >> 11;
            int s = m & 2047;
#pragma unroll
            for (int nt = 0; nt < 4; nt++) {
                int n = n0 + wn * 32 + nt * 8 + 2 * tig;
                float2 v;
                v.x = c[mt][nt][half * 2 + 0] + bias[n + 0];
                v.y = c[mt][nt][half * 2 + 1] + bias[n + 1];
                if (mode == 0) {
                    int which = n >> 10;
                    int rr = n & 1023;
                    int h = rr >> 6;
                    int d = rr & 63;
                    *(float2*)&g_qkv[(size_t)which * 4194304u +
                                     ((size_t)((b << 4) + h) * SEQ + s) * HDIM + d] = v;
                } else {
                    *(float2*)&out[(size_t)m * DMODEL + n] = v;
                }
            }
        }
    }
}

// ---------------------------------------------------------------------------
// Flash attention with tf32 mma.sync — R7 structure (single-buffered Ks/Vs,
// 2 syncs/tile, NO cross-phase register prefetch: R8's prefetch spilled at
// the 128-reg cap and regressed). Only change vs R7: exp2 softmax with
// log2(e) folded into the Q scale (register-neutral).
// Smem floats: Ks[64][68] | Vs[64][72] | Ps[128][68] = 70656 bytes.
// ---------------------------------------------------------------------------
#define KS_STRIDE 68
#define VS_STRIDE 72
#define PS_STRIDE 68
#define FLASH_SMEM ((64*KS_STRIDE + 64*VS_STRIDE + 128*PS_STRIDE) * 4)

__global__ __launch_bounds__(256, 2) void flash_tc_kernel()
{
    extern __shared__ float smf[];
    float* Ks = smf;                                    // [64][KS_STRIDE]
    float* Vs = smf + 64 * KS_STRIDE;                   // [64][VS_STRIDE]
    float* Ps = smf + 64 * KS_STRIDE + 64 * VS_STRIDE;  // [128][PS_STRIDE]

    int tid  = threadIdx.x;
    int w    = tid >> 5;
    int lane = tid & 31;
    int g    = lane >> 2;          // 0..7
    int tig  = lane & 3;           // 0..3

    int q0 = blockIdx.x * 128;
    int h  = blockIdx.y;
    int b  = blockIdx.z;

    // 1/sqrt(64) * log2(e): softmax computed in base-2 domain.
    const float scale = 0.125f * 1.4426950408889634f;

    const float* Qg = g_qkv + 0u * 4194304u + (size_t)((b << 4) + h) * SEQ * HDIM;
    const float* Kg = g_qkv + 1u * 4194304u + (size_t)((b << 4) + h) * SEQ * HDIM;
    const float* Vg = g_qkv + 2u * 4194304u + (size_t)((b << 4) + h) * SEQ * HDIM;

    // Q fragments, register-resident for whole kernel (scale + tf32 folded)
    int qrow = q0 + w * 16;
    float qf[8][4];
#pragma unroll
    for (int kc = 0; kc < 8; kc++) {
        int d0 = kc * 8 + tig;
        qf[kc][0] = f32_to_tf32f(Qg[(size_t)(qrow + g)     * HDIM + d0]     * scale);
        qf[kc][1] = f32_to_tf32f(Qg[(size_t)(qrow + g + 8) * HDIM + d0]     * scale);
        qf[kc][2] = f32_to_tf32f(Qg[(size_t)(qrow + g)     * HDIM + d0 + 4] * scale);
        qf[kc][3] = f32_to_tf32f(Qg[(size_t)(qrow + g + 8) * HDIM + d0 + 4] * scale);
    }

    float m0r = -1e30f, m1r = -1e30f, l0r = 0.f, l1r = 0.f;
    float ov[8][4];
#pragma unroll
    for (int nt = 0; nt < 8; nt++)
#pragma unroll
        for (int q = 0; q < 4; q++) ov[nt][q] = 0.f;

    float* Psw = Ps + w * 16 * PS_STRIDE;   // per-warp private slab

    for (int kt = 0; kt < SEQ / 64; kt++) {
        const float* Kt = Kg + (size_t)kt * 64 * HDIM;
        const float* Vt = Vg + (size_t)kt * 64 * HDIM;

        // Load + convert K and V tiles (aligned float4 paths)
#pragma unroll
        for (int it = 0; it < 4; it++) {
            int j   = tid + it * 256;          // float4 index 0..1023
            int row = j >> 4;
            int c4  = (j & 15) << 2;
            float4 kv = *(const float4*)(Kt + row * HDIM + c4);
            float4 vv = *(const float4*)(Vt + row * HDIM + c4);
            float4 kc4, vc4;
            kc4.x = f32_to_tf32f(kv.x); kc4.y = f32_to_tf32f(kv.y);
            kc4.z = f32_to_tf32f(kv.z); kc4.w = f32_to_tf32f(kv.w);
            vc4.x = f32_to_tf32f(vv.x); vc4.y = f32_to_tf32f(vv.y);
            vc4.z = f32_to_tf32f(vv.z); vc4.w = f32_to_tf32f(vv.w);
            *(float4*)&Ks[row * KS_STRIDE + c4] = kc4;
            *(float4*)&Vs[row * VS_STRIDE + c4] = vc4;
        }
        __syncthreads();

        // S = Q K^T  (per warp: 16 rows x 64 keys, 8 nt x 8 kc mma)
        float sc[8][4];
#pragma unroll
        for (int nt = 0; nt < 8; nt++)
#pragma unroll
            for (int q = 0; q < 4; q++) sc[nt][q] = 0.f;
#pragma unroll
        for (int kc = 0; kc < 8; kc++) {
            int d0 = kc * 8 + tig;
#pragma unroll
            for (int nt = 0; nt < 8; nt++) {
                int key = nt * 8 + g;
                float b0 = Ks[key * KS_STRIDE + d0];
                float b1 = Ks[key * KS_STRIDE + d0 + 4];
                mma_tf32_16x8x8(sc[nt], qf[kc][0], qf[kc][1], qf[kc][2], qf[kc][3], b0, b1);
            }
        }

        // Online softmax (base-2). Rows qrow+g (frag 0,1), qrow+g+8 (frag 2,3).
        float rm0 = -1e30f, rm1 = -1e30f;
#pragma unroll
        for (int nt = 0; nt < 8; nt++) {
            rm0 = fmaxf(rm0, fmaxf(sc[nt][0], sc[nt][1]));
            rm1 = fmaxf(rm1, fmaxf(sc[nt][2], sc[nt][3]));
        }
        rm0 = fmaxf(rm0, __shfl_xor_sync(0xffffffffu, rm0, 1));
        rm0 = fmaxf(rm0, __shfl_xor_sync(0xffffffffu, rm0, 2));
        rm1 = fmaxf(rm1, __shfl_xor_sync(0xffffffffu, rm1, 1));
        rm1 = fmaxf(rm1, __shfl_xor_sync(0xffffffffu, rm1, 2));

        float nm0 = fmaxf(m0r, rm0);
        float nm1 = fmaxf(m1r, rm1);
        float alpha0 = ex2f(m0r - nm0);
        float alpha1 = ex2f(m1r - nm1);
        m0r = nm0; m1r = nm1;

        float rs0 = 0.f, rs1 = 0.f;
#pragma unroll
        for (int nt = 0; nt < 8; nt++) {
            sc[nt][0] = ex2f(sc[nt][0] - nm0);
            sc[nt][1] = ex2f(sc[nt][1] - nm0);
            sc[nt][2] = ex2f(sc[nt][2] - nm1);
            sc[nt][3] = ex2f(sc[nt][3] - nm1);
            rs0 += sc[nt][0] + sc[nt][1];
            rs1 += sc[nt][2] + sc[nt][3];
        }
        rs0 += __shfl_xor_sync(0xffffffffu, rs0, 1);
        rs0 += __shfl_xor_sync(0xffffffffu, rs0, 2);
        rs1 += __shfl_xor_sync(0xffffffffu, rs1, 1);
        rs1 += __shfl_xor_sync(0xffffffffu, rs1, 2);
        l0r = l0r * alpha0 + rs0;
        l1r = l1r * alpha1 + rs1;

        // Rescale O accumulators
#pragma unroll
        for (int nt = 0; nt < 8; nt++) {
            ov[nt][0] *= alpha0; ov[nt][1] *= alpha0;
            ov[nt][2] *= alpha1; ov[nt][3] *= alpha1;
        }

        // Stage P (tf32) into per-warp slab; only this warp touches it.
#pragma unroll
        for (int nt = 0; nt < 8; nt++) {
            float2 p0, p1;
            p0.x = f32_to_tf32f(sc[nt][0]); p0.y = f32_to_tf32f(sc[nt][1]);
            p1.x = f32_to_tf32f(sc[nt][2]); p1.y = f32_to_tf32f(sc[nt][3]);
            *(float2*)&Psw[g       * PS_STRIDE + nt * 8 + 2 * tig] = p0;
            *(float2*)&Psw[(g + 8) * PS_STRIDE + nt * 8 + 2 * tig] = p1;
        }
        __syncwarp();

        // O += P V  (A from Psw: 4 LDS per kc, reused over 8 nt)
#pragma unroll
        for (int kc = 0; kc < 8; kc++) {
            int k0 = kc * 8 + tig;
            float a0 = Psw[g       * PS_STRIDE + k0];
            float a1 = Psw[(g + 8) * PS_STRIDE + k0];
            float a2 = Psw[g       * PS_STRIDE + k0 + 4];
            float a3 = Psw[(g + 8) * PS_STRIDE + k0 + 4];
#pragma unroll
            for (int nt = 0; nt < 8; nt++) {
                float b0 = Vs[k0       * VS_STRIDE + nt * 8 + g];
                float b1 = Vs[(k0 + 4) * VS_STRIDE + nt * 8 + g];
                mma_tf32_16x8x8(ov[nt], a0, a1, a2, a3, b0, b1);
            }
        }
        __syncwarp();
        __syncthreads();   // protect Ks/Vs before next tile's overwrite
    }

    // Epilogue: normalize, write rows qrow+g / qrow+g+8 to [B][S][H*hd]
    float inv0 = 1.0f / l0r;
    float inv1 = 1.0f / l1r;
    int s0 = qrow + g;
    int s1 = qrow + g + 8;
#pragma unroll
    for (int nt = 0; nt < 8; nt++) {
        int d = nt * 8 + 2 * tig;
        float2 v0, v1;
        v0.x = ov[nt][0] * inv0; v0.y = ov[nt][1] * inv0;
        v1.x = ov[nt][2] * inv1; v1.y = ov[nt][3] * inv1;
        *(float2*)&g_attn[((size_t)(b * SEQ + s0)) * DMODEL + h * HDIM + d] = v0;
        *(float2*)&g_attn[((size_t)(b * SEQ + s1)) * DMODEL + h * HDIM + d] = v1;
    }
}

// ---------------------------------------------------------------------------
// Launch
// ---------------------------------------------------------------------------
extern "C" void kernel_launch(void* const* d_in, const int* in_sizes, int n_in,
                              void* d_out, int out_size)
{
    const float* x      = (const float*)d_in[0];
    const float* w_qkv  = (const float*)d_in[1];
    const float* b_qkv  = (const float*)d_in[2];
    const float* w_proj = (const float*)d_in[3];
    const float* b_proj = (const float*)d_in[4];
    float* out = (float*)d_out;

    cudaFuncSetAttribute(flash_tc_kernel, cudaFuncAttributeMaxDynamicSharedMemorySize, FLASH_SMEM);

    gemm_tc_kernel<<<dim3(QKV_N / 128, MTOT / 128), 256>>>(x, w_qkv, b_qkv, nullptr, 0);
    flash_tc_kernel<<<dim3(SEQ / 128, NHEAD, BATCH), 256, FLASH_SMEM>>>();
    gemm_tc_kernel<<<dim3(DMODEL / 128, MTOT / 128), 256>>>(nullptr, w_proj, b_proj, out, 1);
}

// round 11
// speedup vs baseline: 1.3490x; 1.0849x over previous
#include <cuda_runtime.h>
#include <math.h>
#include <stdint.h>

// Problem constants
#define BATCH 2
#define SEQ   2048
#define DMODEL 1024
#define NHEAD 16
#define HDIM  64
#define MTOT  (BATCH*SEQ)            // 4096
#define QKV_N (3*DMODEL)             // 3072
#define GK    1024

// Scratch (allocation-free: __device__ globals)
__device__ float g_qkv[3u * 4194304u];   // [3][B][H][S][hd]  (RNA-rounded tf32 values)
__device__ float g_attn[4194304u];       // [B][S][H*hd]      (RNA-rounded tf32 values)
__device__ float g_rx[4194304u];         // rna(x)
__device__ float g_rwqkv[3145728u];      // rna(w_qkv)
__device__ float g_rwproj[1048576u];     // rna(w_proj)

__device__ __forceinline__ float f32_to_tf32f(float x) {
    uint32_t r;
    asm("cvt.rna.tf32.f32 %0, %1;" : "=r"(r) : "f"(x));
    return __uint_as_float(r);
}

__device__ __forceinline__ float ex2f(float x) {
    float r;
    asm("ex2.approx.ftz.f32 %0, %1;" : "=f"(r) : "f"(x));
    return r;
}

__device__ __forceinline__ uint32_t smem_u32(const void* p) {
    uint32_t a;
    asm("{ .reg .u64 t; cvta.to.shared.u64 t, %1; cvt.u32.u64 %0, t; }" : "=r"(a) : "l"(p));
    return a;
}

__device__ __forceinline__ void cp_async16(uint32_t dst_smem, const void* src) {
    asm volatile("cp.async.cg.shared.global [%0], [%1], 16;" :: "r"(dst_smem), "l"(src));
}
#define CP_COMMIT() asm volatile("cp.async.commit_group;" ::: "memory")
#define CP_WAIT(n)  asm volatile("cp.async.wait_group %0;" :: "n"(n) : "memory")

__device__ __forceinline__ void mma_tf32_16x8x8(float* c,
                                                float a0, float a1, float a2, float a3,
                                                float b0, float b1) {
    asm volatile(
        "mma.sync.aligned.m16n8k8.row.col.f32.tf32.tf32.f32 "
        "{%0,%1,%2,%3}, {%4,%5,%6,%7}, {%8,%9}, {%0,%1,%2,%3};"
        : "+f"(c[0]), "+f"(c[1]), "+f"(c[2]), "+f"(c[3])
        : "r"(__float_as_uint(a0)), "r"(__float_as_uint(a1)),
          "r"(__float_as_uint(a2)), "r"(__float_as_uint(a3)),
          "r"(__float_as_uint(b0)), "r"(__float_as_uint(b1)));
}

// ---------------------------------------------------------------------------
// Prep: RNA-round x, w_qkv, w_proj into scratch (one float4 per thread pass).
// 8388608 floats = 2097152 float4.
// ---------------------------------------------------------------------------
#define PREP_N4 2097152
__global__ __launch_bounds__(256) void prep_round_kernel(
    const float* __restrict__ x,
    const float* __restrict__ w_qkv,
    const float* __restrict__ w_proj)
{
    int i = blockIdx.x * 256 + threadIdx.x;
    if (i >= PREP_N4) return;
    const float4* src;
    float4* dst;
    if (i < 1048576) {                       // x: 4M floats
        src = (const float4*)x + i;
        dst = (float4*)g_rx + i;
    } else if (i < 1048576 + 786432) {       // w_qkv: 3M floats
        src = (const float4*)w_qkv + (i - 1048576);
        dst = (float4*)g_rwqkv + (i - 1048576);
    } else {                                  // w_proj: 1M floats
        src = (const float4*)w_proj + (i - 1048576 - 786432);
        dst = (float4*)g_rwproj + (i - 1048576 - 786432);
    }
    float4 v = *src;
    v.x = f32_to_tf32f(v.x); v.y = f32_to_tf32f(v.y);
    v.z = f32_to_tf32f(v.z); v.w = f32_to_tf32f(v.w);
    *dst = v;
}

// ---------------------------------------------------------------------------
// tf32 mma.sync GEMM, cp.async 3-stage ring (R10 structure, proven pipeline).
// All GMEM operands are pre-RNA-rounded, so cp.async's raw copy + HMMA
// truncation is numerically the identity (R9 numerics).
// mode 0: A=g_rx, W=g_rwqkv, epilogue rna(c+bias) -> g_qkv scatter.
// mode 1: A=g_attn (pre-rounded by flash), W=g_rwproj, plain store to out.
// ---------------------------------------------------------------------------
#define LDS_STRIDE 20
#define G_STG_F   (128 * LDS_STRIDE)
#define G_STG_B   (G_STG_F * 4)
#define GEMM_SMEM (3 * 2 * G_STG_B)

__global__ __launch_bounds__(256, 2) void gemm_tc_kernel(
    const float* __restrict__ bias,
    float* __restrict__ out,
    int mode)
{
    extern __shared__ float gsm[];
    float* As = gsm;                 // [3][G_STG_F]
    float* Bs = gsm + 3 * G_STG_F;   // [3][G_STG_F]

    const float* A = (mode == 0) ? (const float*)g_rx    : (const float*)g_attn;
    const float* W = (mode == 0) ? (const float*)g_rwqkv : (const float*)g_rwproj;

    int tid  = threadIdx.x;
    int wid  = tid >> 5;
    int lane = tid & 31;
    int wm   = wid >> 2;
    int wn   = wid & 3;
    int g    = lane >> 2;
    int tig  = lane & 3;

    int m0 = blockIdx.y * 128;
    int n0 = blockIdx.x * 128;

    int ar0 = tid >> 2;
    int ar1 = ar0 + 64;
    int ac  = (tid & 3) * 4;

    const float* Ab = A + (size_t)m0 * GK + ac;
    const float* Wb = W + (size_t)n0 * GK + ac;

    uint32_t smA = smem_u32(As);
    uint32_t smB = smem_u32(Bs);
    uint32_t dA0 = (uint32_t)(ar0 * LDS_STRIDE + ac) * 4;
    uint32_t dA1 = (uint32_t)(ar1 * LDS_STRIDE + ac) * 4;

    float c[4][4][4];
#pragma unroll
    for (int i = 0; i < 4; i++)
#pragma unroll
        for (int j = 0; j < 4; j++)
#pragma unroll
            for (int q = 0; q < 4; q++) c[i][j][q] = 0.f;

    const int NT = GK / 16;   // 64

    // prologue: issue tile 0 -> stage 0
    {
        cp_async16(smA + dA0, Ab + (size_t)ar0 * GK);
        cp_async16(smA + dA1, Ab + (size_t)ar1 * GK);
        cp_async16(smB + dA0, Wb + (size_t)ar0 * GK);
        cp_async16(smB + dA1, Wb + (size_t)ar1 * GK);
        CP_COMMIT();
    }

    int stg = 0;
    for (int kt = 0; kt < NT; kt++) {
        if (kt + 1 < NT) {
            int nstg = (stg + 1 == 3) ? 0 : stg + 1;
            int ko = (kt + 1) * 16;
            uint32_t aB = smA + nstg * G_STG_B;
            uint32_t bB = smB + nstg * G_STG_B;
            cp_async16(aB + dA0, Ab + (size_t)ar0 * GK + ko);
            cp_async16(aB + dA1, Ab + (size_t)ar1 * GK + ko);
            cp_async16(bB + dA0, Wb + (size_t)ar0 * GK + ko);
            cp_async16(bB + dA1, Wb + (size_t)ar1 * GK + ko);
            CP_COMMIT();
            CP_WAIT(1);
        } else {
            CP_WAIT(0);
        }
        __syncthreads();

        const float* as = As + stg * G_STG_F;
        const float* bs = Bs + stg * G_STG_F;
#pragma unroll
        for (int k8 = 0; k8 < 2; k8++) {
            int kc = k8 * 8 + tig;
            float af[4][4], bf[4][2];
#pragma unroll
            for (int mt = 0; mt < 4; mt++) {
                int r = wm * 64 + mt * 16 + g;
                af[mt][0] = as[(r + 0) * LDS_STRIDE + kc];
                af[mt][1] = as[(r + 8) * LDS_STRIDE + kc];
                af[mt][2] = as[(r + 0) * LDS_STRIDE + kc + 4];
                af[mt][3] = as[(r + 8) * LDS_STRIDE + kc + 4];
            }
#pragma unroll
            for (int nt = 0; nt < 4; nt++) {
                int r = wn * 32 + nt * 8 + g;
                bf[nt][0] = bs[r * LDS_STRIDE + kc];
                bf[nt][1] = bs[r * LDS_STRIDE + kc + 4];
            }
#pragma unroll
            for (int mt = 0; mt < 4; mt++)
#pragma unroll
                for (int nt = 0; nt < 4; nt++)
                    mma_tf32_16x8x8(c[mt][nt],
                                    af[mt][0], af[mt][1], af[mt][2], af[mt][3],
                                    bf[nt][0], bf[nt][1]);
        }
        stg = (stg + 1 == 3) ? 0 : stg + 1;
    }

    // Epilogue
#pragma unroll
    for (int mt = 0; mt < 4; mt++) {
#pragma unroll
        for (int half = 0; half < 2; half++) {
            int m = m0 + wm * 64 + mt * 16 + g + half * 8;
            int b = m >> 11;
            int s = m & 2047;
#pragma unroll
            for (int nt = 0; nt < 4; nt++) {
                int n = n0 + wn * 32 + nt * 8 + 2 * tig;
                float2 v;
                v.x = c[mt][nt][half * 2 + 0] + bias[n + 0];
                v.y = c[mt][nt][half * 2 + 1] + bias[n + 1];
                if (mode == 0) {
                    // RNA-round so downstream cp.async truncation is identity
                    v.x = f32_to_tf32f(v.x);
                    v.y = f32_to_tf32f(v.y);
                    int which = n >> 10;
                    int rr = n & 1023;
                    int h = rr >> 6;
                    int d = rr & 63;
                    *(float2*)&g_qkv[(size_t)which * 4194304u +
                                     ((size_t)((b << 4) + h) * SEQ + s) * HDIM + d] = v;
                } else {
                    *(float2*)&out[(size_t)m * DMODEL + n] = v;
                }
            }
        }
    }
}

// ---------------------------------------------------------------------------
// Flash attention, cp.async 2-stage K/V ring (R10 structure).
// K/V in g_qkv are pre-RNA-rounded -> raw copy + HMMA truncation = identity.
// Q and P fragments keep in-register RNA. Epilogue RNA-rounds g_attn so the
// proj GEMM's cp.async truncation is also the identity.
// Smem: Ks[2][64][68] | Vs[2][64][72] | Ps[128][68] = 106496 B.
// ---------------------------------------------------------------------------
#define KS_STRIDE 68
#define VS_STRIDE 72
#define PS_STRIDE 68
#define KS_STG_F (64 * KS_STRIDE)
#define VS_STG_F (64 * VS_STRIDE)
#define FLASH_SMEM ((2*KS_STG_F + 2*VS_STG_F + 128*PS_STRIDE) * 4)

__global__ __launch_bounds__(256, 2) void flash_tc_kernel()
{
    extern __shared__ float smf[];
    float* KsB = smf;                          // [2][KS_STG_F]
    float* VsB = smf + 2 * KS_STG_F;           // [2][VS_STG_F]
    float* Ps  = smf + 2 * KS_STG_F + 2 * VS_STG_F;  // [128][PS_STRIDE]

    int tid  = threadIdx.x;
    int w    = tid >> 5;
    int lane = tid & 31;
    int g    = lane >> 2;          // 0..7
    int tig  = lane & 3;           // 0..3

    int q0 = blockIdx.x * 128;
    int h  = blockIdx.y;
    int b  = blockIdx.z;

    // 1/sqrt(64) * log2(e): softmax in base-2 domain.
    const float scale = 0.125f * 1.4426950408889634f;

    const float* Qg = g_qkv + 0u * 4194304u + (size_t)((b << 4) + h) * SEQ * HDIM;
    const float* Kg = g_qkv + 1u * 4194304u + (size_t)((b << 4) + h) * SEQ * HDIM;
    const float* Vg = g_qkv + 2u * 4194304u + (size_t)((b << 4) + h) * SEQ * HDIM;

    uint32_t smK = smem_u32(KsB);
    uint32_t smV = smem_u32(VsB);

    // per-thread cp.async coords: 4 rows x one float4 each for K and V
    int lrow = tid >> 4;             // 0..15
    int lc4  = (tid & 15) << 2;      // 0,4,...,60

    // Q fragments, register-resident (scale folded, RNA re-round after scale)
    int qrow = q0 + w * 16;
    float qf[8][4];
#pragma unroll
    for (int kc = 0; kc < 8; kc++) {
        int d0 = kc * 8 + tig;
        qf[kc][0] = f32_to_tf32f(Qg[(size_t)(qrow + g)     * HDIM + d0]     * scale);
        qf[kc][1] = f32_to_tf32f(Qg[(size_t)(qrow + g + 8) * HDIM + d0]     * scale);
        qf[kc][2] = f32_to_tf32f(Qg[(size_t)(qrow + g)     * HDIM + d0 + 4] * scale);
        qf[kc][3] = f32_to_tf32f(Qg[(size_t)(qrow + g + 8) * HDIM + d0 + 4] * scale);
    }

    float m0r = -1e30f, m1r = -1e30f, l0r = 0.f, l1r = 0.f;
    float ov[8][4];
#pragma unroll
    for (int nt = 0; nt < 8; nt++)
#pragma unroll
        for (int q = 0; q < 4; q++) ov[nt][q] = 0.f;

    float* Psw = Ps + w * 16 * PS_STRIDE;   // per-warp private slab

    const int NT = SEQ / 64;   // 32

    // prologue: issue tile 0 -> stage 0
    {
#pragma unroll
        for (int it = 0; it < 4; it++) {
            int row = lrow + it * 16;
            cp_async16(smK + (uint32_t)(row * KS_STRIDE + lc4) * 4,
                       Kg + (size_t)row * HDIM + lc4);
            cp_async16(smV + (uint32_t)(row * VS_STRIDE + lc4) * 4,
                       Vg + (size_t)row * HDIM + lc4);
        }
        CP_COMMIT();
    }

    for (int kt = 0; kt < NT; kt++) {
        int cur = kt & 1;
        if (kt + 1 < NT) {
            const float* Kn = Kg + (size_t)(kt + 1) * 64 * HDIM;
            const float* Vn = Vg + (size_t)(kt + 1) * 64 * HDIM;
            uint32_t kB = smK + (cur ^ 1) * (KS_STG_F * 4);
            uint32_t vB = smV + (cur ^ 1) * (VS_STG_F * 4);
#pragma unroll
            for (int it = 0; it < 4; it++) {
                int row = lrow + it * 16;
                cp_async16(kB + (uint32_t)(row * KS_STRIDE + lc4) * 4,
                           Kn + (size_t)row * HDIM + lc4);
                cp_async16(vB + (uint32_t)(row * VS_STRIDE + lc4) * 4,
                           Vn + (size_t)row * HDIM + lc4);
            }
            CP_COMMIT();
            CP_WAIT(1);
        } else {
            CP_WAIT(0);
        }
        __syncthreads();

        const float* Ks = KsB + cur * KS_STG_F;
        const float* Vs = VsB + cur * VS_STG_F;

        // S = Q K^T
        float sc[8][4];
#pragma unroll
        for (int nt = 0; nt < 8; nt++)
#pragma unroll
            for (int q = 0; q < 4; q++) sc[nt][q] = 0.f;
#pragma unroll
        for (int kc = 0; kc < 8; kc++) {
            int d0 = kc * 8 + tig;
#pragma unroll
            for (int nt = 0; nt < 8; nt++) {
                int key = nt * 8 + g;
                float b0 = Ks[key * KS_STRIDE + d0];
                float b1 = Ks[key * KS_STRIDE + d0 + 4];
                mma_tf32_16x8x8(sc[nt], qf[kc][0], qf[kc][1], qf[kc][2], qf[kc][3], b0, b1);
            }
        }

        // Online softmax (base-2).
        float rm0 = -1e30f, rm1 = -1e30f;
#pragma unroll
        for (int nt = 0; nt < 8; nt++) {
            rm0 = fmaxf(rm0, fmaxf(sc[nt][0], sc[nt][1]));
            rm1 = fmaxf(rm1, fmaxf(sc[nt][2], sc[nt][3]));
        }
        rm0 = fmaxf(rm0, __shfl_xor_sync(0xffffffffu, rm0, 1));
        rm0 = fmaxf(rm0, __shfl_xor_sync(0xffffffffu, rm0, 2));
        rm1 = fmaxf(rm1, __shfl_xor_sync(0xffffffffu, rm1, 1));
        rm1 = fmaxf(rm1, __shfl_xor_sync(0xffffffffu, rm1, 2));

        float nm0 = fmaxf(m0r, rm0);
        float nm1 = fmaxf(m1r, rm1);
        float alpha0 = ex2f(m0r - nm0);
        float alpha1 = ex2f(m1r - nm1);
        m0r = nm0; m1r = nm1;

        float rs0 = 0.f, rs1 = 0.f;
#pragma unroll
        for (int nt = 0; nt < 8; nt++) {
            sc[nt][0] = ex2f(sc[nt][0] - nm0);
            sc[nt][1] = ex2f(sc[nt][1] - nm0);
            sc[nt][2] = ex2f(sc[nt][2] - nm1);
            sc[nt][3] = ex2f(sc[nt][3] - nm1);
            rs0 += sc[nt][0] + sc[nt][1];
            rs1 += sc[nt][2] + sc[nt][3];
        }
        rs0 += __shfl_xor_sync(0xffffffffu, rs0, 1);
        rs0 += __shfl_xor_sync(0xffffffffu, rs0, 2);
        rs1 += __shfl_xor_sync(0xffffffffu, rs1, 1);
        rs1 += __shfl_xor_sync(0xffffffffu, rs1, 2);
        l0r = l0r * alpha0 + rs0;
        l1r = l1r * alpha1 + rs1;

#pragma unroll
        for (int nt = 0; nt < 8; nt++) {
            ov[nt][0] *= alpha0; ov[nt][1] *= alpha0;
            ov[nt][2] *= alpha1; ov[nt][3] *= alpha1;
        }

        // Stage P (RNA tf32) into per-warp slab
#pragma unroll
        for (int nt = 0; nt < 8; nt++) {
            float2 p0, p1;
            p0.x = f32_to_tf32f(sc[nt][0]); p0.y = f32_to_tf32f(sc[nt][1]);
            p1.x = f32_to_tf32f(sc[nt][2]); p1.y = f32_to_tf32f(sc[nt][3]);
            *(float2*)&Psw[g       * PS_STRIDE + nt * 8 + 2 * tig] = p0;
            *(float2*)&Psw[(g + 8) * PS_STRIDE + nt * 8 + 2 * tig] = p1;
        }
        __syncwarp();

        // O += P V
#pragma unroll
        for (int kc = 0; kc < 8; kc++) {
            int k0 = kc * 8 + tig;
            float a0 = Psw[g       * PS_STRIDE + k0];
            float a1 = Psw[(g + 8) * PS_STRIDE + k0];
            float a2 = Psw[g       * PS_STRIDE + k0 + 4];
            float a3 = Psw[(g + 8) * PS_STRIDE + k0 + 4];
#pragma unroll
            for (int nt = 0; nt < 8; nt++) {
                float b0 = Vs[k0       * VS_STRIDE + nt * 8 + g];
                float b1 = Vs[(k0 + 4) * VS_STRIDE + nt * 8 + g];
                mma_tf32_16x8x8(ov[nt], a0, a1, a2, a3, b0, b1);
            }
        }
        __syncthreads();   // all warps done with stage cur before it's refilled
    }

    // Epilogue: normalize, RNA-round (proj cp.async identity), store.
    float inv0 = 1.0f / l0r;
    float inv1 = 1.0f / l1r;
    int s0 = qrow + g;
    int s1 = qrow + g + 8;
#pragma unroll
    for (int nt = 0; nt < 8; nt++) {
        int d = nt * 8 + 2 * tig;
        float2 v0, v1;
        v0.x = f32_to_tf32f(ov[nt][0] * inv0); v0.y = f32_to_tf32f(ov[nt][1] * inv0);
        v1.x = f32_to_tf32f(ov[nt][2] * inv1); v1.y = f32_to_tf32f(ov[nt][3] * inv1);
        *(float2*)&g_attn[((size_t)(b * SEQ + s0)) * DMODEL + h * HDIM + d] = v0;
        *(float2*)&g_attn[((size_t)(b * SEQ + s1)) * DMODEL + h * HDIM + d] = v1;
    }
}

// ---------------------------------------------------------------------------
// Launch
// ---------------------------------------------------------------------------
extern "C" void kernel_launch(void* const* d_in, const int* in_sizes, int n_in,
                              void* d_out, int out_size)
{
    const float* x      = (const float*)d_in[0];
    const float* w_qkv  = (const float*)d_in[1];
    const float* b_qkv  = (const float*)d_in[2];
    const float* w_proj = (const float*)d_in[3];
    const float* b_proj = (const float*)d_in[4];
    float* out = (float*)d_out;

    cudaFuncSetAttribute(gemm_tc_kernel, cudaFuncAttributeMaxDynamicSharedMemorySize, GEMM_SMEM);
    cudaFuncSetAttribute(flash_tc_kernel, cudaFuncAttributeMaxDynamicSharedMemorySize, FLASH_SMEM);

    prep_round_kernel<<<(PREP_N4 + 255) / 256, 256>>>(x, w_qkv, w_proj);
    gemm_tc_kernel<<<dim3(QKV_N / 128, MTOT / 128), 256, GEMM_SMEM>>>(b_qkv, nullptr, 0);
    flash_tc_kernel<<<dim3(SEQ / 128, NHEAD, BATCH), 256, FLASH_SMEM>>>();
    gemm_tc_kernel<<<dim3(DMODEL / 128, MTOT / 128), 256, GEMM_SMEM>>>(b_proj, out, 1);
}

// round 12
// speedup vs baseline: 1.3672x; 1.0135x over previous
#include <cuda_runtime.h>
#include <math.h>
#include <stdint.h>

// Problem constants
#define BATCH 2
#define SEQ   2048
#define DMODEL 1024
#define NHEAD 16
#define HDIM  64
#define MTOT  (BATCH*SEQ)            // 4096
#define QKV_N (3*DMODEL)             // 3072
#define GK    1024

// Scratch (allocation-free: __device__ globals)
__device__ float g_qkv[3u * 4194304u];   // [3][B][H][S][hd]  (RNA-rounded tf32 values)
__device__ float g_attn[4194304u];       // [B][S][H*hd]      (RNA-rounded tf32 values)
__device__ float g_rx[4194304u];         // rna(x)
__device__ float g_rwqkv[3145728u];      // rna(w_qkv)
__device__ float g_rwproj[1048576u];     // rna(w_proj)

__device__ __forceinline__ float f32_to_tf32f(float x) {
    uint32_t r;
    asm("cvt.rna.tf32.f32 %0, %1;" : "=r"(r) : "f"(x));
    return __uint_as_float(r);
}

__device__ __forceinline__ float ex2f(float x) {
    float r;
    asm("ex2.approx.ftz.f32 %0, %1;" : "=f"(r) : "f"(x));
    return r;
}

__device__ __forceinline__ uint32_t smem_u32(const void* p) {
    uint32_t a;
    asm("{ .reg .u64 t; cvta.to.shared.u64 t, %1; cvt.u32.u64 %0, t; }" : "=r"(a) : "l"(p));
    return a;
}

__device__ __forceinline__ void cp_async16(uint32_t dst_smem, const void* src) {
    asm volatile("cp.async.cg.shared.global [%0], [%1], 16;" :: "r"(dst_smem), "l"(src));
}
#define CP_COMMIT() asm volatile("cp.async.commit_group;" ::: "memory")
#define CP_WAIT(n)  asm volatile("cp.async.wait_group %0;" :: "n"(n) : "memory")

__device__ __forceinline__ void mma_tf32_16x8x8(float* c,
                                                float a0, float a1, float a2, float a3,
                                                float b0, float b1) {
    asm volatile(
        "mma.sync.aligned.m16n8k8.row.col.f32.tf32.tf32.f32 "
        "{%0,%1,%2,%3}, {%4,%5,%6,%7}, {%8,%9}, {%0,%1,%2,%3};"
        : "+f"(c[0]), "+f"(c[1]), "+f"(c[2]), "+f"(c[3])
        : "r"(__float_as_uint(a0)), "r"(__float_as_uint(a1)),
          "r"(__float_as_uint(a2)), "r"(__float_as_uint(a3)),
          "r"(__float_as_uint(b0)), "r"(__float_as_uint(b1)));
}

// ---------------------------------------------------------------------------
// Prep: RNA-round x, w_qkv, w_proj into scratch.
// ---------------------------------------------------------------------------
#define PREP_N4 2097152
__global__ __launch_bounds__(256) void prep_round_kernel(
    const float* __restrict__ x,
    const float* __restrict__ w_qkv,
    const float* __restrict__ w_proj)
{
    int i = blockIdx.x * 256 + threadIdx.x;
    if (i >= PREP_N4) return;
    const float4* src;
    float4* dst;
    if (i < 1048576) {
        src = (const float4*)x + i;
        dst = (float4*)g_rx + i;
    } else if (i < 1048576 + 786432) {
        src = (const float4*)w_qkv + (i - 1048576);
        dst = (float4*)g_rwqkv + (i - 1048576);
    } else {
        src = (const float4*)w_proj + (i - 1048576 - 786432);
        dst = (float4*)g_rwproj + (i - 1048576 - 786432);
    }
    float4 v = *src;
    v.x = f32_to_tf32f(v.x); v.y = f32_to_tf32f(v.y);
    v.z = f32_to_tf32f(v.z); v.w = f32_to_tf32f(v.w);
    *dst = v;
}

// ---------------------------------------------------------------------------
// tf32 mma.sync GEMM, cp.async 3-stage ring, K-tile 32, depth-2 prefetch.
// Issue order per iter: wait(tile kt ready) -> barrier (all warps done with
// stage stg-1) -> issue tile kt+2 into stage (stg+2)%3 == just-freed stage
// -> compute stage stg. One barrier/iter, two tiles always in flight.
// Smem: 3 stages x (A 18432B + B 18432B) = 110592B -> 2 CTAs/SM.
// ---------------------------------------------------------------------------
#define GKT 32
#define LDS_STRIDE 36
#define G_STG_F   (128 * LDS_STRIDE)
#define G_STG_B   (G_STG_F * 4)
#define GEMM_SMEM (3 * 2 * G_STG_B)

__global__ __launch_bounds__(256, 2) void gemm_tc_kernel(
    const float* __restrict__ bias,
    float* __restrict__ out,
    int mode)
{
    extern __shared__ float gsm[];
    float* As = gsm;                 // [3][G_STG_F]
    float* Bs = gsm + 3 * G_STG_F;   // [3][G_STG_F]

    const float* A = (mode == 0) ? (const float*)g_rx    : (const float*)g_attn;
    const float* W = (mode == 0) ? (const float*)g_rwqkv : (const float*)g_rwproj;

    int tid  = threadIdx.x;
    int wid  = tid >> 5;
    int lane = tid & 31;
    int wm   = wid >> 2;
    int wn   = wid & 3;
    int g    = lane >> 2;
    int tig  = lane & 3;

    int m0 = blockIdx.y * 128;
    int n0 = blockIdx.x * 128;

    // cp.async coords: 4 chunks per matrix per tile; chunk p: row=tid>>3 + p*32,
    // col4=(tid&7)*4 within the 32-wide k-tile.
    int crow = tid >> 3;             // 0..31
    int cc4  = (tid & 7) << 2;       // 0,4,...,28

    const float* Ab = A + (size_t)m0 * GK;
    const float* Wb = W + (size_t)n0 * GK;

    uint32_t smA = smem_u32(As);
    uint32_t smB = smem_u32(Bs);

    float c[4][4][4];
#pragma unroll
    for (int i = 0; i < 4; i++)
#pragma unroll
        for (int j = 0; j < 4; j++)
#pragma unroll
            for (int q = 0; q < 4; q++) c[i][j][q] = 0.f;

    const int NT = GK / GKT;   // 32

    // issue helper (macro-ish lambda): tile t -> stage s
    auto issue_tile = [&](int t, int s) {
        int ko = t * GKT;
        uint32_t aB = smA + s * G_STG_B;
        uint32_t bB = smB + s * G_STG_B;
#pragma unroll
        for (int p = 0; p < 4; p++) {
            int row = crow + p * 32;
            uint32_t doff = (uint32_t)(row * LDS_STRIDE + cc4) * 4;
            cp_async16(aB + doff, Ab + (size_t)row * GK + ko + cc4);
            cp_async16(bB + doff, Wb + (size_t)row * GK + ko + cc4);
        }
        CP_COMMIT();
    };

    // prologue: tiles 0,1 -> stages 0,1
    issue_tile(0, 0);
    issue_tile(1, 1);

    int stg = 0;
    for (int kt = 0; kt < NT; kt++) {
        if (kt + 1 < NT) { CP_WAIT(1); } else { CP_WAIT(0); }
        __syncthreads();                    // all warps done reading stage stg-1

        if (kt + 2 < NT) {
            int ws = stg + 2; if (ws >= 3) ws -= 3;
            issue_tile(kt + 2, ws);         // writes just-freed stage: safe
        }

        const float* as = As + stg * G_STG_F;
        const float* bs = Bs + stg * G_STG_F;
#pragma unroll
        for (int k8 = 0; k8 < 4; k8++) {
            int kc = k8 * 8 + tig;
            float af[4][4], bf[4][2];
#pragma unroll
            for (int mt = 0; mt < 4; mt++) {
                int r = wm * 64 + mt * 16 + g;
                af[mt][0] = as[(r + 0) * LDS_STRIDE + kc];
                af[mt][1] = as[(r + 8) * LDS_STRIDE + kc];
                af[mt][2] = as[(r + 0) * LDS_STRIDE + kc + 4];
                af[mt][3] = as[(r + 8) * LDS_STRIDE + kc + 4];
            }
#pragma unroll
            for (int nt = 0; nt < 4; nt++) {
                int r = wn * 32 + nt * 8 + g;
                bf[nt][0] = bs[r * LDS_STRIDE + kc];
                bf[nt][1] = bs[r * LDS_STRIDE + kc + 4];
            }
#pragma unroll
            for (int mt = 0; mt < 4; mt++)
#pragma unroll
                for (int nt = 0; nt < 4; nt++)
                    mma_tf32_16x8x8(c[mt][nt],
                                    af[mt][0], af[mt][1], af[mt][2], af[mt][3],
                                    bf[nt][0], bf[nt][1]);
        }
        stg = stg + 1; if (stg >= 3) stg = 0;
    }

    // Epilogue
#pragma unroll
    for (int mt = 0; mt < 4; mt++) {
#pragma unroll
        for (int half = 0; half < 2; half++) {
            int m = m0 + wm * 64 + mt * 16 + g + half * 8;
            int b = m >> 11;
            int s = m & 2047;
#pragma unroll
            for (int nt = 0; nt < 4; nt++) {
                int n = n0 + wn * 32 + nt * 8 + 2 * tig;
                float2 v;
                v.x = c[mt][nt][half * 2 + 0] + bias[n + 0];
                v.y = c[mt][nt][half * 2 + 1] + bias[n + 1];
                if (mode == 0) {
                    v.x = f32_to_tf32f(v.x);
                    v.y = f32_to_tf32f(v.y);
                    int which = n >> 10;
                    int rr = n & 1023;
                    int h = rr >> 6;
                    int d = rr & 63;
                    *(float2*)&g_qkv[(size_t)which * 4194304u +
                                     ((size_t)((b << 4) + h) * SEQ + s) * HDIM + d] = v;
                } else {
                    *(float2*)&out[(size_t)m * DMODEL + n] = v;
                }
            }
        }
    }
}

// ---------------------------------------------------------------------------
// Flash attention, cp.async 2-stage K/V ring — unchanged from R11 passing.
// ---------------------------------------------------------------------------
#define KS_STRIDE 68
#define VS_STRIDE 72
#define PS_STRIDE 68
#define KS_STG_F (64 * KS_STRIDE)
#define VS_STG_F (64 * VS_STRIDE)
#define FLASH_SMEM ((2*KS_STG_F + 2*VS_STG_F + 128*PS_STRIDE) * 4)

__global__ __launch_bounds__(256, 2) void flash_tc_kernel()
{
    extern __shared__ float smf[];
    float* KsB = smf;                          // [2][KS_STG_F]
    float* VsB = smf + 2 * KS_STG_F;           // [2][VS_STG_F]
    float* Ps  = smf + 2 * KS_STG_F + 2 * VS_STG_F;  // [128][PS_STRIDE]

    int tid  = threadIdx.x;
    int w    = tid >> 5;
    int lane = tid & 31;
    int g    = lane >> 2;          // 0..7
    int tig  = lane & 3;           // 0..3

    int q0 = blockIdx.x * 128;
    int h  = blockIdx.y;
    int b  = blockIdx.z;

    const float scale = 0.125f * 1.4426950408889634f;

    const float* Qg = g_qkv + 0u * 4194304u + (size_t)((b << 4) + h) * SEQ * HDIM;
    const float* Kg = g_qkv + 1u * 4194304u + (size_t)((b << 4) + h) * SEQ * HDIM;
    const float* Vg = g_qkv + 2u * 4194304u + (size_t)((b << 4) + h) * SEQ * HDIM;

    uint32_t smK = smem_u32(KsB);
    uint32_t smV = smem_u32(VsB);

    int lrow = tid >> 4;             // 0..15
    int lc4  = (tid & 15) << 2;      // 0,4,...,60

    int qrow = q0 + w * 16;
    float qf[8][4];
#pragma unroll
    for (int kc = 0; kc < 8; kc++) {
        int d0 = kc * 8 + tig;
        qf[kc][0] = f32_to_tf32f(Qg[(size_t)(qrow + g)     * HDIM + d0]     * scale);
        qf[kc][1] = f32_to_tf32f(Qg[(size_t)(qrow + g + 8) * HDIM + d0]     * scale);
        qf[kc][2] = f32_to_tf32f(Qg[(size_t)(qrow + g)     * HDIM + d0 + 4] * scale);
        qf[kc][3] = f32_to_tf32f(Qg[(size_t)(qrow + g + 8) * HDIM + d0 + 4] * scale);
    }

    float m0r = -1e30f, m1r = -1e30f, l0r = 0.f, l1r = 0.f;
    float ov[8][4];
#pragma unroll
    for (int nt = 0; nt < 8; nt++)
#pragma unroll
        for (int q = 0; q < 4; q++) ov[nt][q] = 0.f;

    float* Psw = Ps + w * 16 * PS_STRIDE;

    const int NT = SEQ / 64;   // 32

    {
#pragma unroll
        for (int it = 0; it < 4; it++) {
            int row = lrow + it * 16;
            cp_async16(smK + (uint32_t)(row * KS_STRIDE + lc4) * 4,
                       Kg + (size_t)row * HDIM + lc4);
            cp_async16(smV + (uint32_t)(row * VS_STRIDE + lc4) * 4,
                       Vg + (size_t)row * HDIM + lc4);
        }
        CP_COMMIT();
    }

    for (int kt = 0; kt < NT; kt++) {
        int cur = kt & 1;
        if (kt + 1 < NT) {
            const float* Kn = Kg + (size_t)(kt + 1) * 64 * HDIM;
            const float* Vn = Vg + (size_t)(kt + 1) * 64 * HDIM;
            uint32_t kB = smK + (cur ^ 1) * (KS_STG_F * 4);
            uint32_t vB = smV + (cur ^ 1) * (VS_STG_F * 4);
#pragma unroll
            for (int it = 0; it < 4; it++) {
                int row = lrow + it * 16;
                cp_async16(kB + (uint32_t)(row * KS_STRIDE + lc4) * 4,
                           Kn + (size_t)row * HDIM + lc4);
                cp_async16(vB + (uint32_t)(row * VS_STRIDE + lc4) * 4,
                           Vn + (size_t)row * HDIM + lc4);
            }
            CP_COMMIT();
            CP_WAIT(1);
        } else {
            CP_WAIT(0);
        }
        __syncthreads();

        const float* Ks = KsB + cur * KS_STG_F;
        const float* Vs = VsB + cur * VS_STG_F;

        float sc[8][4];
#pragma unroll
        for (int nt = 0; nt < 8; nt++)
#pragma unroll
            for (int q = 0; q < 4; q++) sc[nt][q] = 0.f;
#pragma unroll
        for (int kc = 0; kc < 8; kc++) {
            int d0 = kc * 8 + tig;
#pragma unroll
            for (int nt = 0; nt < 8; nt++) {
                int key = nt * 8 + g;
                float b0 = Ks[key * KS_STRIDE + d0];
                float b1 = Ks[key * KS_STRIDE + d0 + 4];
                mma_tf32_16x8x8(sc[nt], qf[kc][0], qf[kc][1], qf[kc][2], qf[kc][3], b0, b1);
            }
        }

        float rm0 = -1e30f, rm1 = -1e30f;
#pragma unroll
        for (int nt = 0; nt < 8; nt++) {
            rm0 = fmaxf(rm0, fmaxf(sc[nt][0], sc[nt][1]));
            rm1 = fmaxf(rm1, fmaxf(sc[nt][2], sc[nt][3]));
        }
        rm0 = fmaxf(rm0, __shfl_xor_sync(0xffffffffu, rm0, 1));
        rm0 = fmaxf(rm0, __shfl_xor_sync(0xffffffffu, rm0, 2));
        rm1 = fmaxf(rm1, __shfl_xor_sync(0xffffffffu, rm1, 1));
        rm1 = fmaxf(rm1, __shfl_xor_sync(0xffffffffu, rm1, 2));

        float nm0 = fmaxf(m0r, rm0);
        float nm1 = fmaxf(m1r, rm1);
        float alpha0 = ex2f(m0r - nm0);
        float alpha1 = ex2f(m1r - nm1);
        m0r = nm0; m1r = nm1;

        float rs0 = 0.f, rs1 = 0.f;
#pragma unroll
        for (int nt = 0; nt < 8; nt++) {
            sc[nt][0] = ex2f(sc[nt][0] - nm0);
            sc[nt][1] = ex2f(sc[nt][1] - nm0);
            sc[nt][2] = ex2f(sc[nt][2] - nm1);
            sc[nt][3] = ex2f(sc[nt][3] - nm1);
            rs0 += sc[nt][0] + sc[nt][1];
            rs1 += sc[nt][2] + sc[nt][3];
        }
        rs0 += __shfl_xor_sync(0xffffffffu, rs0, 1);
        rs0 += __shfl_xor_sync(0xffffffffu, rs0, 2);
        rs1 += __shfl_xor_sync(0xffffffffu, rs1, 1);
        rs1 += __shfl_xor_sync(0xffffffffu, rs1, 2);
        l0r = l0r * alpha0 + rs0;
        l1r = l1r * alpha1 + rs1;

#pragma unroll
        for (int nt = 0; nt < 8; nt++) {
            ov[nt][0] *= alpha0; ov[nt][1] *= alpha0;
            ov[nt][2] *= alpha1; ov[nt][3] *= alpha1;
        }

#pragma unroll
        for (int nt = 0; nt < 8; nt++) {
            float2 p0, p1;
            p0.x = f32_to_tf32f(sc[nt][0]); p0.y = f32_to_tf32f(sc[nt][1]);
            p1.x = f32_to_tf32f(sc[nt][2]); p1.y = f32_to_tf32f(sc[nt][3]);
            *(float2*)&Psw[g       * PS_STRIDE + nt * 8 + 2 * tig] = p0;
            *(float2*)&Psw[(g + 8) * PS_STRIDE + nt * 8 + 2 * tig] = p1;
        }
        __syncwarp();

#pragma unroll
        for (int kc = 0; kc < 8; kc++) {
            int k0 = kc * 8 + tig;
            float a0 = Psw[g       * PS_STRIDE + k0];
            float a1 = Psw[(g + 8) * PS_STRIDE + k0];
            float a2 = Psw[g       * PS_STRIDE + k0 + 4];
            float a3 = Psw[(g + 8) * PS_STRIDE + k0 + 4];
#pragma unroll
            for (int nt = 0; nt < 8; nt++) {
                float b0 = Vs[k0       * VS_STRIDE + nt * 8 + g];
                float b1 = Vs[(k0 + 4) * VS_STRIDE + nt * 8 + g];
                mma_tf32_16x8x8(ov[nt], a0, a1, a2, a3, b0, b1);
            }
        }
        __syncthreads();
    }

    float inv0 = 1.0f / l0r;
    float inv1 = 1.0f / l1r;
    int s0 = qrow + g;
    int s1 = qrow + g + 8;
#pragma unroll
    for (int nt = 0; nt < 8; nt++) {
        int d = nt * 8 + 2 * tig;
        float2 v0, v1;
        v0.x = f32_to_tf32f(ov[nt][0] * inv0); v0.y = f32_to_tf32f(ov[nt][1] * inv0);
        v1.x = f32_to_tf32f(ov[nt][2] * inv1); v1.y = f32_to_tf32f(ov[nt][3] * inv1);
        *(float2*)&g_attn[((size_t)(b * SEQ + s0)) * DMODEL + h * HDIM + d] = v0;
        *(float2*)&g_attn[((size_t)(b * SEQ + s1)) * DMODEL + h * HDIM + d] = v1;
    }
}

// ---------------------------------------------------------------------------
// Launch
// ---------------------------------------------------------------------------
extern "C" void kernel_launch(void* const* d_in, const int* in_sizes, int n_in,
                              void* d_out, int out_size)
{
    const float* x      = (const float*)d_in[0];
    const float* w_qkv  = (const float*)d_in[1];
    const float* b_qkv  = (const float*)d_in[2];
    const float* w_proj = (const float*)d_in[3];
    const float* b_proj = (const float*)d_in[4];
    float* out = (float*)d_out;

    cudaFuncSetAttribute(gemm_tc_kernel, cudaFuncAttributeMaxDynamicSharedMemorySize, GEMM_SMEM);
    cudaFuncSetAttribute(flash_tc_kernel, cudaFuncAttributeMaxDynamicSharedMemorySize, FLASH_SMEM);

    prep_round_kernel<<<(PREP_N4 + 255) / 256, 256>>>(x, w_qkv, w_proj);
    gemm_tc_kernel<<<dim3(QKV_N / 128, MTOT / 128), 256, GEMM_SMEM>>>(b_qkv, nullptr, 0);
    flash_tc_kernel<<<dim3(SEQ / 128, NHEAD, BATCH), 256, FLASH_SMEM>>>();
    gemm_tc_kernel<<<dim3(DMODEL / 128, MTOT / 128), 256, GEMM_SMEM>>>(b_proj, out, 1);
}